// round 7
// baseline (speedup 1.0000x reference)
#include <cuda_runtime.h>
#include <cuda_bf16.h>

#define MAX_NODES 1048576
__device__ float g_nodecol[MAX_NODES];   // packed nodes[:,0], rebuilt every launch

// out[i] = w_node * nodes[i, 0] + b_node, and pack nodes[:,0] into g_nodecol.
__global__ void tmp_init_kernel(const float* __restrict__ nodes,
                                const float* __restrict__ w_node_p,
                                const float* __restrict__ b_node_p,
                                float* __restrict__ out,
                                int n_nodes, int d_node) {
    int i = blockIdx.x * blockDim.x + threadIdx.x;
    if (i < n_nodes) {
        float wn = __ldg(w_node_p);
        float bn = __ldg(b_node_p);
        float v  = __ldg(nodes + (size_t)i * d_node);
        g_nodecol[i] = v;
        out[i] = wn * v + bn;
    }
}

// Warp-cooperative: each warp handles 32 consecutive edges.
// Edge rows read as 4 coalesced float4 sweeps; element 0 redistributed via
// shfl. Sender gather hits the packed 400KB g_nodecol (L1-cacheable, dense:
// 32 useful values per 128B line) instead of the 51MB strided nodes array.
// Safe to __ldg: g_nodecol is written only by the init kernel and L1 is
// flushed at every kernel-launch boundary on sm_103a.
__global__ __launch_bounds__(256)
void tmp_edge_kernel(const float* __restrict__ edges,
                     const int*   __restrict__ senders,
                     const int*   __restrict__ receivers,
                     const float* __restrict__ w_node_p,
                     const float* __restrict__ w_edge_p,
                     float* __restrict__ out,
                     int n_edges, int d_edge) {
    const float wn = __ldg(w_node_p);
    const float we = __ldg(w_edge_p);

    const int tid         = blockIdx.x * blockDim.x + threadIdx.x;
    const int warp_global = tid >> 5;
    const int lane        = tid & 31;
    const int base        = warp_global * 32;

    if (base >= n_edges) return;

    if (base + 32 <= n_edges && d_edge == 16) {
        // Coalesced index loads: one edge per lane.
        const int e = base + lane;
        const int s = __ldcs(senders + e);
        const int r = __ldcs(receivers + e);

        // 4 coalesced float4 sweeps over the warp's 2KB of edge rows.
        const float4* ef4 = (const float4*)edges;
        const size_t f4base = (size_t)base * 4;
        float4 q0 = __ldcs(ef4 + f4base + 0 * 32 + lane);
        float4 q1 = __ldcs(ef4 + f4base + 1 * 32 + lane);
        float4 q2 = __ldcs(ef4 + f4base + 2 * 32 + lane);
        float4 q3 = __ldcs(ef4 + f4base + 3 * 32 + lane);

        // Gather from the packed column via the read-only path (L1-cached).
        const float nv = __ldg(&g_nodecol[s]);

        // Lane L wants edge base+L: sweep L/8, source lane (L%8)*4, comp .x.
        const int src = (lane & 7) * 4;
        float t0 = __shfl_sync(0xffffffffu, q0.x, src);
        float t1 = __shfl_sync(0xffffffffu, q1.x, src);
        float t2 = __shfl_sync(0xffffffffu, q2.x, src);
        float t3 = __shfl_sync(0xffffffffu, q3.x, src);
        const int sel = lane >> 3;
        float ev = (sel == 0) ? t0 : (sel == 1) ? t1 : (sel == 2) ? t2 : t3;

        atomicAdd(out + r, fmaf(we, ev, wn * nv));
    } else {
        // Tail / generic path
        const int e = base + lane;
        if (e < n_edges) {
            const int s = __ldg(senders + e);
            const int r = __ldg(receivers + e);
            const float ev = __ldg(edges + (size_t)e * d_edge);
            const float nv = __ldg(&g_nodecol[s]);
            atomicAdd(out + r, fmaf(we, ev, wn * nv));
        }
    }
}

extern "C" void kernel_launch(void* const* d_in, const int* in_sizes, int n_in,
                              void* d_out, int out_size) {
    const float* nodes     = (const float*)d_in[0];
    const float* edges     = (const float*)d_in[1];
    const int*   senders   = (const int*)  d_in[2];
    const int*   receivers = (const int*)  d_in[3];
    const float* w_node    = (const float*)d_in[4];
    const float* w_edge    = (const float*)d_in[5];
    const float* b_node    = (const float*)d_in[6];
    float*       out       = (float*)d_out;

    const int n_nodes = out_size;
    const int n_edges = in_sizes[2];
    const int d_node  = in_sizes[0] / n_nodes;   // 128
    const int d_edge  = in_sizes[1] / n_edges;   // 16

    // 1) Seed output and pack nodes[:,0] into g_nodecol.
    {
        int threads = 256;
        int blocks  = (n_nodes + threads - 1) / threads;
        tmp_init_kernel<<<blocks, threads>>>(nodes, w_node, b_node, out, n_nodes, d_node);
    }

    // 2) Scatter-add messages (32 edges per warp, warp-cooperative).
    {
        int threads = 256;                        // 8 warps/block
        int edges_per_block = (threads / 32) * 32;
        int blocks = (n_edges + edges_per_block - 1) / edges_per_block;
        tmp_edge_kernel<<<blocks, threads>>>(edges, senders, receivers,
                                             w_node, w_edge, out,
                                             n_edges, d_edge);
    }
}